// round 1
// baseline (speedup 1.0000x reference)
#include <cuda_runtime.h>
#include <cstdint>

// GraphAttentionLayer: B=2, N=4096, Fin=Fout=64, k=20
// Pipeline:
//   kA: Wh = x@W, f1 = Wh@a[:64], f2 = Wh@a[64:], pos4 = (x,y,z,|p|^2)
//   kB: exact kNN (top-20 by (d2, index), matching jax.lax.top_k tie semantics)
//   kC: per-node 20-way masked softmax + neighbor aggregation + relu(pos@Wp+bp) + elu

#define NB    2
#define NN    4096
#define FD    64
#define KNN   20
#define TOT   (NB*NN)

typedef unsigned long long ull;

__device__ float  g_Wh[TOT*FD];
__device__ float  g_f1[TOT];
__device__ float  g_f2[TOT];
__device__ float4 g_pos4[TOT];
__device__ int    g_knn[TOT*KNN];

// ---------------------------------------------------------------------------
// Kernel A: Wh, f1, f2, pos4
// block = 256 threads handles 16 rows; each thread computes 4 output columns.
// ---------------------------------------------------------------------------
__global__ void kA(const float* __restrict__ x, const float* __restrict__ pos,
                   const float* __restrict__ W, const float* __restrict__ a) {
    __shared__ float4 sW4[64*16];   // W as float4 per (k, colgroup)
    __shared__ float  sX[16*64];    // 16 rows of x
    __shared__ float  sa[128];
    int tid = threadIdx.x;
    int rowbase = blockIdx.x * 16;

    const float4* W4 = (const float4*)W;
    #pragma unroll
    for (int i = 0; i < 4; i++) sW4[tid + i*256] = W4[tid + i*256];
    ((float4*)sX)[tid] = ((const float4*)(x + (size_t)rowbase*FD))[tid];
    if (tid < 128) sa[tid] = a[tid];
    if (tid < 16) {
        int node = rowbase + tid;
        float px = pos[node*3+0], py = pos[node*3+1], pz = pos[node*3+2];
        float sq = fmaf(pz, pz, fmaf(py, py, px*px));
        g_pos4[node] = make_float4(px, py, pz, sq);
    }
    __syncthreads();

    int rl = tid >> 4;        // local row 0..15
    int c4 = tid & 15;        // column group (4 cols each)
    float acc0 = 0.f, acc1 = 0.f, acc2 = 0.f, acc3 = 0.f;
    #pragma unroll
    for (int kk = 0; kk < 64; kk++) {
        float  xv = sX[rl*64 + kk];
        float4 w  = sW4[kk*16 + c4];
        acc0 = fmaf(xv, w.x, acc0);
        acc1 = fmaf(xv, w.y, acc1);
        acc2 = fmaf(xv, w.z, acc2);
        acc3 = fmaf(xv, w.w, acc3);
    }
    int row = rowbase + rl;
    ((float4*)g_Wh)[row*16 + c4] = make_float4(acc0, acc1, acc2, acc3);

    int cb = c4*4;
    float p1 = acc0*sa[cb]    + acc1*sa[cb+1]    + acc2*sa[cb+2]    + acc3*sa[cb+3];
    float p2 = acc0*sa[64+cb] + acc1*sa[64+cb+1] + acc2*sa[64+cb+2] + acc3*sa[64+cb+3];
    #pragma unroll
    for (int o = 8; o; o >>= 1) {
        p1 += __shfl_xor_sync(0xFFFFFFFFu, p1, o);
        p2 += __shfl_xor_sync(0xFFFFFFFFu, p2, o);
    }
    if (c4 == 0) { g_f1[row] = p1; g_f2[row] = p2; }
}

// ---------------------------------------------------------------------------
// Kernel B: exact kNN. One warp per query node.
// key = (monotone-ordered d2 bits << 32) | index  -> identical ordering and
// tie-breaking (lower index first) as jax.lax.top_k on -d2.
// ---------------------------------------------------------------------------
__device__ __forceinline__ ull dist_key(float4 pq, float4 p, int m) {
    float dot = fmaf(pq.z, p.z, fmaf(pq.y, p.y, pq.x*p.x));
    float d2  = fmaf(-2.0f, dot, pq.w + p.w);       // sq_n + sq_m - 2*dot (ref formula)
    unsigned u = __float_as_uint(d2);
    u ^= ((unsigned)((int)u >> 31)) | 0x80000000u;  // monotone float->uint
    return ((ull)u << 32) | (unsigned)m;
}

__global__ void kB() {
    int warp = threadIdx.x >> 5, lane = threadIdx.x & 31;
    int qid   = blockIdx.x * 8 + warp;       // 0..8191
    int batch = qid >> 12;
    int qn    = qid & (NN - 1);
    const float4* pb = g_pos4 + batch*NN;
    float4 pq = pb[qn];

    // per-lane sorted list of the 8 smallest keys among this lane's candidates
    ull lst[8];
    #pragma unroll
    for (int i = 0; i < 8; i++) lst[i] = ~0ull;

    #pragma unroll 4
    for (int m = lane; m < NN; m += 32) {
        float4 p = __ldg(&pb[m]);
        ull key = dist_key(pq, p, m);
        if (m != qn && key < lst[7]) {
            // branchless sorted insert (descending index order keeps old values live)
            #pragma unroll
            for (int i = 7; i > 0; i--)
                lst[i] = (key < lst[i-1]) ? lst[i-1] : (key < lst[i] ? key : lst[i]);
            lst[0] = (key < lst[0]) ? key : lst[0];
        }
    }

    // 20-round warp k-way merge of 32 sorted lists
    int ptr = 0;
    ull winner = 0;
    #pragma unroll 1
    for (int r = 0; r < KNN; r++) {
        ull cand = (ptr < 8) ? lst[ptr] : ~0ull;
        ull w = cand;
        #pragma unroll
        for (int o = 16; o; o >>= 1) {
            ull other = __shfl_xor_sync(0xFFFFFFFFu, w, o);
            w = (other < w) ? other : w;
        }
        if (cand == w) ptr++;       // keys are unique -> exactly one owner
        if (lane == r) winner = w;
    }

    // Safe unless some lane exhausted its 8-entry list (>=8 of the top-20 on
    // one lane; P ~ 3e-7 per lane). Fallback: exact serial scan.
    unsigned unsafe = __ballot_sync(0xFFFFFFFFu, ptr >= 8);
    int* dst = g_knn + qid*KNN;
    if (!unsafe) {
        if (lane < KNN) dst[lane] = (int)(winner & 0xFFFFFFFFu);
    } else if (lane == 0) {
        ull bl[KNN];
        #pragma unroll
        for (int i = 0; i < KNN; i++) bl[i] = ~0ull;
        for (int m = 0; m < NN; m++) {
            if (m == qn) continue;
            ull key = dist_key(pq, pb[m], m);
            if (key < bl[KNN-1]) {
                int p = KNN-1;
                while (p > 0 && key < bl[p-1]) { bl[p] = bl[p-1]; p--; }
                bl[p] = key;
            }
        }
        for (int j = 0; j < KNN; j++) dst[j] = (int)(bl[j] & 0xFFFFFFFFu);
    }
}

// ---------------------------------------------------------------------------
// Kernel C: softmax over 20 neighbors + aggregation + pos projection + elu.
// One warp per query node; lane handles channels {lane, lane+32}.
// Non-neighbor softmax terms are exact fp32 zeros in the reference
// (exp(-9e15 - max) underflows), so summing only the 20 neighbors is exact.
// ---------------------------------------------------------------------------
__global__ void kC(const float* __restrict__ pos, const float* __restrict__ Wp,
                   const float* __restrict__ bp, float* __restrict__ out) {
    int warp = threadIdx.x >> 5, lane = threadIdx.x & 31;
    int qid   = blockIdx.x * 8 + warp;
    int batch = qid >> 12;

    float f1n = g_f1[qid];
    int nb = 0;
    float e = -1e30f;
    if (lane < KNN) {
        nb = g_knn[qid*KNN + lane];
        float ev = f1n + g_f2[batch*NN + nb];
        e = (ev > 0.f) ? ev : 0.2f*ev;          // LeakyReLU(0.2)
    }
    float mx = e;
    #pragma unroll
    for (int o = 16; o; o >>= 1) mx = fmaxf(mx, __shfl_xor_sync(0xFFFFFFFFu, mx, o));
    float ex = (lane < KNN) ? expf(e - mx) : 0.f;
    float s = ex;
    #pragma unroll
    for (int o = 16; o; o >>= 1) s += __shfl_xor_sync(0xFFFFFFFFu, s, o);
    float attn = ex / s;

    const float* whb = g_Wh + (size_t)batch*NN*FD;
    float h0 = 0.f, h1 = 0.f;
    #pragma unroll
    for (int j = 0; j < KNN; j++) {
        int   jj = __shfl_sync(0xFFFFFFFFu, nb,   j);
        float aj = __shfl_sync(0xFFFFFFFFu, attn, j);
        const float* wr = whb + jj*FD;
        h0 = fmaf(aj, __ldg(wr + lane),      h0);
        h1 = fmaf(aj, __ldg(wr + lane + 32), h1);
    }

    float px = pos[qid*3+0], py = pos[qid*3+1], pz = pos[qid*3+2];
    float pp0 = fmaf(pz, Wp[128+lane],    fmaf(py, Wp[64+lane],    fmaf(px, Wp[lane],    bp[lane])));
    float pp1 = fmaf(pz, Wp[128+lane+32], fmaf(py, Wp[64+lane+32], fmaf(px, Wp[lane+32], bp[lane+32])));
    h0 += fmaxf(pp0, 0.f);
    h1 += fmaxf(pp1, 0.f);

    out[(size_t)qid*FD + lane]      = (h0 > 0.f) ? h0 : expm1f(h0);   // ELU
    out[(size_t)qid*FD + lane + 32] = (h1 > 0.f) ? h1 : expm1f(h1);
}

// ---------------------------------------------------------------------------
extern "C" void kernel_launch(void* const* d_in, const int* in_sizes, int n_in,
                              void* d_out, int out_size) {
    const float* x   = (const float*)d_in[0];
    const float* pos = (const float*)d_in[1];
    const float* W   = (const float*)d_in[2];
    const float* a   = (const float*)d_in[3];
    const float* Wp  = (const float*)d_in[4];
    const float* bp  = (const float*)d_in[5];
    float* out = (float*)d_out;

    kA<<<TOT/16, 256>>>(x, pos, W, a);
    kB<<<TOT/8, 256>>>();
    kC<<<TOT/8, 256>>>(pos, Wp, bp, out);
}

// round 11
// speedup vs baseline: 2.0661x; 2.0661x over previous
#include <cuda_runtime.h>
#include <cstdint>

// GraphAttentionLayer: B=2, N=4096, Fin=Fout=64, k=20
//   kA: Wh = x@W, f1 = Wh@a[:64], f2 = Wh@a[64:], pos4 = (x,y,z,|p|^2)
//   kB: exact kNN via warp-collective sorted top-20 (one entry per lane),
//       threshold = exact global-20th-so-far, all compares in the
//       monotone-ordered uint domain (no float/NaN sentinel hazard)
//   kC: 20-way softmax + neighbor aggregation + relu(pos@Wp+bp) + elu

#define NB    2
#define NN    4096
#define FD    64
#define KNN   20
#define TOT   (NB*NN)

typedef unsigned long long ull;

__device__ float  g_Wh[TOT*FD];
__device__ float  g_f1[TOT];
__device__ float  g_f2[TOT];
__device__ float4 g_pos4[TOT];
__device__ int    g_knn[TOT*KNN];

// ---------------------------------------------------------------------------
// Kernel A: Wh, f1, f2, pos4. 512 threads = 32 rows per block.
// ---------------------------------------------------------------------------
__global__ void kA(const float* __restrict__ x, const float* __restrict__ pos,
                   const float* __restrict__ W, const float* __restrict__ a) {
    __shared__ float4 sW4[64*16];   // 16 KB: W as float4 per (k, colgroup)
    __shared__ float  sX[32*64];    // 8 KB: 32 rows of x
    __shared__ float  sa[128];
    int tid = threadIdx.x;
    int rowbase = blockIdx.x * 32;

    const float4* W4 = (const float4*)W;
    sW4[tid]       = W4[tid];
    sW4[tid + 512] = W4[tid + 512];
    ((float4*)sX)[tid] = ((const float4*)(x + (size_t)rowbase*FD))[tid];
    if (tid < 128) sa[tid] = a[tid];
    if (tid < 32) {
        int node = rowbase + tid;
        float px = pos[node*3+0], py = pos[node*3+1], pz = pos[node*3+2];
        float sq = fmaf(pz, pz, fmaf(py, py, px*px));
        g_pos4[node] = make_float4(px, py, pz, sq);
    }
    __syncthreads();

    int rl = tid >> 4;        // local row 0..31
    int c4 = tid & 15;        // column group (4 cols each)
    float acc0 = 0.f, acc1 = 0.f, acc2 = 0.f, acc3 = 0.f;
    #pragma unroll
    for (int kk = 0; kk < 64; kk++) {
        float  xv = sX[rl*64 + kk];
        float4 w  = sW4[kk*16 + c4];
        acc0 = fmaf(xv, w.x, acc0);
        acc1 = fmaf(xv, w.y, acc1);
        acc2 = fmaf(xv, w.z, acc2);
        acc3 = fmaf(xv, w.w, acc3);
    }
    int row = rowbase + rl;
    ((float4*)g_Wh)[row*16 + c4] = make_float4(acc0, acc1, acc2, acc3);

    int cb = c4*4;
    float p1 = acc0*sa[cb]    + acc1*sa[cb+1]    + acc2*sa[cb+2]    + acc3*sa[cb+3];
    float p2 = acc0*sa[64+cb] + acc1*sa[64+cb+1] + acc2*sa[64+cb+2] + acc3*sa[64+cb+3];
    #pragma unroll
    for (int o = 8; o; o >>= 1) {
        p1 += __shfl_xor_sync(0xFFFFFFFFu, p1, o);
        p2 += __shfl_xor_sync(0xFFFFFFFFu, p2, o);
    }
    if (c4 == 0) { g_f1[row] = p1; g_f2[row] = p2; }
}

// ---------------------------------------------------------------------------
// Kernel B: exact kNN. One warp per query node.
// Warp holds the exact sorted top-20 (by (ordered d2 bits, index) -- identical
// ordering & tie-break as jax.lax.top_k on -d2), one entry per lane; lanes
// 0..19 are the answer, lane 19's top word is the filter threshold.
// All ordering logic is in the monotone-ordered uint domain:
//   obits(d2) is strictly increasing in d2, and the 0xFFFFFFFF list sentinel
//   compares above every real value (obits(+inf)=0xFF800000), so the initial
//   "accept everything" state needs no special case.
// d2 formula is bit-identical to the round-1 passing kernel.
// ---------------------------------------------------------------------------
__device__ __forceinline__ float dist_f(float4 pq, float4 p) {
    float dot = fmaf(pq.z, p.z, fmaf(pq.y, p.y, pq.x*p.x));
    return fmaf(-2.0f, dot, pq.w + p.w);            // sq_n + sq_m - 2*dot
}
__device__ __forceinline__ unsigned obits(float d2) {
    unsigned u = __float_as_uint(d2);
    return u ^ (((unsigned)((int)u >> 31)) | 0x80000000u);  // monotone float->uint
}

__global__ void kB() {
    const unsigned FULL = 0xFFFFFFFFu;
    int warp = threadIdx.x >> 5, lane = threadIdx.x & 31;
    int qid   = blockIdx.x * 8 + warp;       // 0..8191
    int batch = qid >> 12;
    int qn    = qid & (NN - 1);
    const float4* pp = g_pos4 + batch*NN;
    float4 pq = pp[qn];

    ull      L     = ~0ull;        // lane's sorted-list entry (ascending by lane)
    unsigned tau_u = 0xFFFFFFFFu;  // ordered bits of current 20th-best (lane 19)

    #pragma unroll 1
    for (int base = 0; base < NN; base += 64) {
        int mA = base + lane, mB = base + 32 + lane;
        float4 p4A = __ldg(&pp[mA]);
        float4 p4B = __ldg(&pp[mB]);
        unsigned uA = obits(dist_f(pq, p4A));
        unsigned uB = obits(dist_f(pq, p4B));
        unsigned ba = __ballot_sync(FULL, (uA <= tau_u) && (mA != qn));
        unsigned bb = __ballot_sync(FULL, (uB <= tau_u) && (mB != qn));

        #pragma unroll 1
        while (ba | bb) {
            unsigned uu; int mm;
            if (ba) {
                int src = __ffs(ba) - 1; ba &= ba - 1;
                uu = __shfl_sync(FULL, uA, src); mm = base + src;
            } else {
                int src = __ffs(bb) - 1; bb &= bb - 1;
                uu = __shfl_sync(FULL, uB, src); mm = base + 32 + src;
            }
            if (uu > tau_u) continue;             // tau tightened since ballot (uniform)

            ull K = ((ull)uu << 32) | (unsigned)mm;
            // warp shift-up insert into the sorted-ascending list
            ull up = __shfl_up_sync(FULL, L, 1);
            bool c = K < L;
            unsigned cbm = __ballot_sync(FULL, c);
            bool cm1 = (lane > 0) && ((cbm >> (lane - 1)) & 1u);
            L = c ? (cm1 ? up : K) : L;
            // threshold = exact 20th-so-far (lane 19), raw ordered bits
            tau_u = __shfl_sync(FULL, (unsigned)(L >> 32), KNN - 1);
        }
    }

    if (lane < KNN) g_knn[qid*KNN + lane] = (int)(L & 0xFFFFFFFFu);
}

// ---------------------------------------------------------------------------
// Kernel C: softmax over 20 neighbors + aggregation + pos projection + elu.
// Non-neighbor softmax terms are exact fp32 zeros in the reference
// (exp(-9e15 - max) underflows), so summing only the 20 neighbors is exact.
// ---------------------------------------------------------------------------
__global__ void kC(const float* __restrict__ pos, const float* __restrict__ Wp,
                   const float* __restrict__ bp, float* __restrict__ out) {
    int warp = threadIdx.x >> 5, lane = threadIdx.x & 31;
    int qid   = blockIdx.x * 8 + warp;
    int batch = qid >> 12;

    float f1n = g_f1[qid];
    int nb = 0;
    float e = -1e30f;
    if (lane < KNN) {
        nb = g_knn[qid*KNN + lane];
        float ev = f1n + g_f2[batch*NN + nb];
        e = (ev > 0.f) ? ev : 0.2f*ev;          // LeakyReLU(0.2)
    }
    float mx = e;
    #pragma unroll
    for (int o = 16; o; o >>= 1) mx = fmaxf(mx, __shfl_xor_sync(0xFFFFFFFFu, mx, o));
    float ex = (lane < KNN) ? expf(e - mx) : 0.f;
    float s = ex;
    #pragma unroll
    for (int o = 16; o; o >>= 1) s += __shfl_xor_sync(0xFFFFFFFFu, s, o);
    float attn = ex / s;

    const float* whb = g_Wh + (size_t)batch*NN*FD;
    float h0 = 0.f, h1 = 0.f;
    #pragma unroll
    for (int j = 0; j < KNN; j++) {
        int   jj = __shfl_sync(0xFFFFFFFFu, nb,   j);
        float aj = __shfl_sync(0xFFFFFFFFu, attn, j);
        const float* wr = whb + jj*FD;
        h0 = fmaf(aj, __ldg(wr + lane),      h0);
        h1 = fmaf(aj, __ldg(wr + lane + 32), h1);
    }

    float px = pos[qid*3+0], py = pos[qid*3+1], pz = pos[qid*3+2];
    float pp0 = fmaf(pz, Wp[128+lane],    fmaf(py, Wp[64+lane],    fmaf(px, Wp[lane],    bp[lane])));
    float pp1 = fmaf(pz, Wp[128+lane+32], fmaf(py, Wp[64+lane+32], fmaf(px, Wp[lane+32], bp[lane+32])));
    h0 += fmaxf(pp0, 0.f);
    h1 += fmaxf(pp1, 0.f);

    out[(size_t)qid*FD + lane]      = (h0 > 0.f) ? h0 : expm1f(h0);   // ELU
    out[(size_t)qid*FD + lane + 32] = (h1 > 0.f) ? h1 : expm1f(h1);
}

// ---------------------------------------------------------------------------
extern "C" void kernel_launch(void* const* d_in, const int* in_sizes, int n_in,
                              void* d_out, int out_size) {
    const float* x   = (const float*)d_in[0];
    const float* pos = (const float*)d_in[1];
    const float* W   = (const float*)d_in[2];
    const float* a   = (const float*)d_in[3];
    const float* Wp  = (const float*)d_in[4];
    const float* bp  = (const float*)d_in[5];
    float* out = (float*)d_out;

    kA<<<TOT/32, 512>>>(x, pos, W, a);
    kB<<<TOT/8, 256>>>();
    kC<<<TOT/8, 256>>>(pos, Wp, bp, out);
}